// round 3
// baseline (speedup 1.0000x reference)
#include <cuda_runtime.h>

#define NP 16384   // N_POINTS
#define NS 8192    // N_SAMPLES
#define KCHUNK 256
#define NKCH (NS / KCHUNK)   // 32 k-chunks
#define TPB 256
#define IPT 4
#define IBLK (TPB * IPT)     // 1024 i-points per block
#define NIB (NS / IBLK)      // 8 i-blocks

// Scratch (no device allocations allowed)
__device__ float4 g_b[NS];                 // (-2bx, -2by, -2bz, ||b||^2)
__device__ float  g_ax[NS], g_ay[NS], g_az[NS], g_sqa[NS];
__device__ float  g_partial[NKCH * NS];    // partial mins [kchunk][i]

__global__ void gather_kernel(const float* __restrict__ a,
                              const float* __restrict__ b,
                              const int* __restrict__ a_idx,
                              const int* __restrict__ b_idx,
                              float* __restrict__ out) {
    int i = blockIdx.x * blockDim.x + threadIdx.x;
    if (i == 0) *out = 0.0f;   // d_out is poisoned; zero it before reduce
    if (i >= NS) return;

    int ia = a_idx[i];
    float ax = a[ia], ay = a[NP + ia], az = a[2 * NP + ia];
    g_ax[i] = ax; g_ay[i] = ay; g_az[i] = az;
    g_sqa[i] = ax * ax + ay * ay + az * az;

    int ib = b_idx[i];
    float bx = b[ib], by = b[NP + ib], bz = b[2 * NP + ib];
    g_b[i] = make_float4(-2.0f * bx, -2.0f * by, -2.0f * bz,
                         bx * bx + by * by + bz * bz);
}

__global__ __launch_bounds__(TPB) void dist_kernel() {
    __shared__ float4 sb[KCHUNK];
    const int t = threadIdx.x;
    const int ibase = blockIdx.x * IBLK + t;
    const int kbase = blockIdx.y * KCHUNK;

    sb[t] = g_b[kbase + t];

    float ax[IPT], ay[IPT], az[IPT], mn[IPT];
    #pragma unroll
    for (int r = 0; r < IPT; r++) {
        int i = ibase + r * TPB;
        ax[r] = g_ax[i]; ay[r] = g_ay[i]; az[r] = g_az[i];
        mn[r] = 3.4e38f;
    }
    __syncthreads();

    #pragma unroll 4
    for (int k = 0; k < KCHUNK; k++) {
        float4 bv = sb[k];
        #pragma unroll
        for (int r = 0; r < IPT; r++) {
            // ||b||^2 - 2 b.a  (a's ||a||^2 added in the final reduce)
            float d = fmaf(bv.x, ax[r], fmaf(bv.y, ay[r], fmaf(bv.z, az[r], bv.w)));
            mn[r] = fminf(mn[r], d);
        }
    }

    #pragma unroll
    for (int r = 0; r < IPT; r++)
        g_partial[blockIdx.y * NS + ibase + r * TPB] = mn[r];
}

__global__ __launch_bounds__(256) void reduce_kernel(float* __restrict__ out) {
    int i = blockIdx.x * blockDim.x + threadIdx.x;
    float m = g_partial[i];
    #pragma unroll
    for (int c = 1; c < NKCH; c++)
        m = fminf(m, g_partial[c * NS + i]);
    float v = m + g_sqa[i];

    __shared__ float ssum[8];
    #pragma unroll
    for (int o = 16; o > 0; o >>= 1)
        v += __shfl_down_sync(0xffffffffu, v, o);
    if ((threadIdx.x & 31) == 0) ssum[threadIdx.x >> 5] = v;
    __syncthreads();
    if (threadIdx.x < 8) {
        v = ssum[threadIdx.x];
        #pragma unroll
        for (int o = 4; o > 0; o >>= 1)
            v += __shfl_down_sync(0xffu, v, o);
        if (threadIdx.x == 0) atomicAdd(out, v);
    }
}

extern "C" void kernel_launch(void* const* d_in, const int* in_sizes, int n_in,
                              void* d_out, int out_size) {
    const float* a  = (const float*)d_in[0];
    const float* b  = (const float*)d_in[1];
    const int*   ai = (const int*)d_in[2];
    const int*   bi = (const int*)d_in[3];
    float* out = (float*)d_out;

    gather_kernel<<<(NS + 255) / 256, 256>>>(a, b, ai, bi, out);
    dist_kernel<<<dim3(NIB, NKCH), TPB>>>();
    reduce_kernel<<<NS / 256, 256>>>(out);
}